// round 8
// baseline (speedup 1.0000x reference)
#include <cuda_runtime.h>
#include <math.h>

#define T_  512
#define B_  2048
#define I_  24
#define H_  20

// Scratch xg[t][b][u] = float4(i,f,g,o). 8 pad timesteps so recur's depth-4
// prefetch (reads up to t ~ mylen+6) stays in-bounds.
__device__ float4 g_xg[(size_t)(T_ + 8) * B_ * H_];
// h[t*B+b][u] for the head pass.
__device__ float  g_h[(size_t)T_ * B_ * H_];

__device__ __forceinline__ float tanhx(float x) {
    float r; asm("tanh.approx.f32 %0,%1;" : "=f"(r) : "f"(x)); return r;
}
__device__ __forceinline__ float sigx(float x) {   // sigmoid via HW tanh
    return fmaf(0.5f, tanhx(0.5f * x), 0.5f);
}

// ---------------------------------------------------------------------------
// Kernel 1: xg = x @ W_ih^T + (b_ih+b_hh) for t < len[b].
// Persistent-slab: block = 8 b-columns x 20 units (160 thr), loops over t.
// Weights live in registers (96 floats, loaded ONCE per block). Columns are
// strided 256 apart so block trip counts are balanced (sorted lengths).
// Stores: thread (j,u) writes float4 (i,f,g,o) at (t, b_j, u) -> consecutive
// tid = consecutive 16B = coalesced, directly in recur's preferred layout.
// x rows: 20 threads of a column read the same addresses -> L1 broadcast.
// ---------------------------------------------------------------------------
__global__ __launch_bounds__(160, 3)
void xg_kernel(const float* __restrict__ x,
               const int*   __restrict__ lens,
               const float* __restrict__ Wih,
               const float* __restrict__ bih,
               const float* __restrict__ bhh)
{
    const int tid = threadIdx.x;
    const int j   = tid / H_;                 // column 0..7
    const int u   = tid % H_;                 // unit 0..19
    const int r   = blockIdx.x;               // 0..255
    const int b   = r + j * 256;

    const int lenmax = lens[r];               // longest column in slab (j=0)
    const int mylen  = lens[b];

    float w0[I_], w1[I_], w2[I_], w3[I_];
    #pragma unroll
    for (int k = 0; k < I_; k++) {
        w0[k] = Wih[(0*H_ + u) * I_ + k];
        w1[k] = Wih[(1*H_ + u) * I_ + k];
        w2[k] = Wih[(2*H_ + u) * I_ + k];
        w3[k] = Wih[(3*H_ + u) * I_ + k];
    }
    float4 bias;
    bias.x = bih[0*H_ + u] + bhh[0*H_ + u];
    bias.y = bih[1*H_ + u] + bhh[1*H_ + u];
    bias.z = bih[2*H_ + u] + bhh[2*H_ + u];
    bias.w = bih[3*H_ + u] + bhh[3*H_ + u];

    const float4* xp  = (const float4*)(x + (size_t)b * I_);   // row (0, b)
    const size_t  xstr = (size_t)B_ * I_ / 4;                  // per-t, float4s
    float4*       op  = &g_xg[(size_t)b * H_ + u];             // (0, b, u)
    const size_t  ostr = (size_t)B_ * H_;

    for (int t = 0; t < lenmax; t++) {
        if (t < mylen) {
            float4 a = bias;
            #pragma unroll
            for (int q = 0; q < 6; q++) {
                float4 v = xp[q];             // L1-broadcast across the column
                a.x = fmaf(w0[4*q+0], v.x, a.x); a.x = fmaf(w0[4*q+1], v.y, a.x);
                a.x = fmaf(w0[4*q+2], v.z, a.x); a.x = fmaf(w0[4*q+3], v.w, a.x);
                a.y = fmaf(w1[4*q+0], v.x, a.y); a.y = fmaf(w1[4*q+1], v.y, a.y);
                a.y = fmaf(w1[4*q+2], v.z, a.y); a.y = fmaf(w1[4*q+3], v.w, a.y);
                a.z = fmaf(w2[4*q+0], v.x, a.z); a.z = fmaf(w2[4*q+1], v.y, a.z);
                a.z = fmaf(w2[4*q+2], v.z, a.z); a.z = fmaf(w2[4*q+3], v.w, a.z);
                a.w = fmaf(w3[4*q+0], v.x, a.w); a.w = fmaf(w3[4*q+1], v.y, a.w);
                a.w = fmaf(w3[4*q+2], v.z, a.w); a.w = fmaf(w3[4*q+3], v.w, a.w);
            }
            *op = a;                          // coalesced across the block
        }
        xp += xstr;
        op += ostr;
    }
}

// ---------------------------------------------------------------------------
// Kernel 2: recurrence, one warp per batch element, t < len[b] only.
// Gate loads coalesced (320B/warp-step) and prefetched FOUR steps ahead via
// a manually-rotated register buffer (unroll-by-4). Steps past mylen may
// compute on garbage (in-bounds pad reads) but never store.
// ---------------------------------------------------------------------------
__global__ __launch_bounds__(128, 4)
void recur_kernel(const int*   __restrict__ lens,
                  const float* __restrict__ Whh)
{
    const int lane = threadIdx.x & 31;
    const int wid  = threadIdx.x >> 5;
    const int j    = blockIdx.x;
    const int b    = (wid < 2) ? (2*j + wid) : (2047 - 2*j - (wid - 2));
    const int uu   = (lane < H_) ? lane : 0;      // lanes 20..31 mirror u=0

    float wi[H_], wf[H_], wg[H_], wo[H_];
    #pragma unroll
    for (int k = 0; k < H_; k++) {
        wi[k] = Whh[(0*H_ + uu) * H_ + k];
        wf[k] = Whh[(1*H_ + uu) * H_ + k];
        wg[k] = Whh[(2*H_ + uu) * H_ + k];
        wo[k] = Whh[(3*H_ + uu) * H_ + k];
    }
    const int mylen = lens[b];                    // >= 1

    float h = 0.0f, c = 0.0f;

    const float4* xp = &g_xg[(size_t)b * H_ + uu];
    const size_t  xstride = (size_t)B_ * H_;
    float4 q0 = xp[0];
    float4 q1 = xp[xstride];
    float4 q2 = xp[2*xstride];
    float4 q3 = xp[3*xstride];
    xp += 4 * xstride;                            // next refill row

    float* hp = &g_h[(size_t)b * H_ + lane];

    #define RSTEP(QBUF, TOFF)                                            \
    {                                                                    \
        float ai = QBUF.x, af = QBUF.y, ag = QBUF.z, ao = QBUF.w;        \
        _Pragma("unroll")                                                \
        for (int k = 0; k < H_; k++) {                                   \
            float hk = __shfl_sync(0xffffffffu, h, k);                   \
            ai = fmaf(wi[k], hk, ai);                                    \
            af = fmaf(wf[k], hk, af);                                    \
            ag = fmaf(wg[k], hk, ag);                                    \
            ao = fmaf(wo[k], hk, ao);                                    \
        }                                                                \
        c = fmaf(sigx(af), c, sigx(ai) * tanhx(ag));                     \
        h = sigx(ao) * tanhx(c);                                         \
        if (lane < H_ && (t + TOFF) < mylen)                             \
            hp[(size_t)(t + TOFF) * (B_ * H_)] = h;                      \
        QBUF = *xp;                               /* refill t+TOFF+4 */  \
        xp += xstride;                                                   \
    }

    for (int t = 0; t < mylen; t += 4) {
        RSTEP(q0, 0)
        RSTEP(q1, 1)
        RSTEP(q2, 2)
        RSTEP(q3, 3)
    }
    #undef RSTEP
}

// ---------------------------------------------------------------------------
// Kernel 3: heads + padding over the full [T, B] grid.
// ---------------------------------------------------------------------------
__global__ __launch_bounds__(256)
void head_kernel(const int*   __restrict__ lens,
                 const float* __restrict__ Wa,
                 const float* __restrict__ ba,
                 const float* __restrict__ Wb,
                 const float* __restrict__ bb,
                 float* __restrict__ out)
{
    const int idx = blockIdx.x * 256 + threadIdx.x;   // t*B + b
    const int b   = idx & (B_ - 1);
    const int t   = idx >> 11;

    float za = ba[0], zb = bb[0];
    if (t < lens[b]) {
        float4 hq[5];
        const float4* hp = (const float4*)&g_h[(size_t)idx * H_];
        #pragma unroll
        for (int q = 0; q < 5; q++) hq[q] = hp[q];
        const float* hv = (const float*)hq;
        #pragma unroll
        for (int k = 0; k < H_; k++) {
            za = fmaf(hv[k], Wa[k], za);
            zb = fmaf(hv[k], Wb[k], zb);
        }
    }
    out[idx] = __expf(za);
    out[(size_t)T_ * B_ + idx] =
        fmaxf(zb, 0.0f) + __logf(1.0f + __expf(-fabsf(zb)));
}

extern "C" void kernel_launch(void* const* d_in, const int* in_sizes, int n_in,
                              void* d_out, int out_size)
{
    const float *x = 0, *Wih = 0, *Whh = 0, *bih = 0, *bhh = 0;
    const float *Wa = 0, *ba = 0, *Wb = 0, *bb = 0;
    const int *lens = 0;
    int seen80 = 0, seen20 = 0, seen1 = 0;
    for (int i = 0; i < n_in; i++) {
        int s = in_sizes[i];
        if      (s == T_ * B_ * I_) x    = (const float*)d_in[i];
        else if (s == B_)           lens = (const int*)d_in[i];
        else if (s == 4*H_ * I_)    Wih  = (const float*)d_in[i];
        else if (s == 4*H_ * H_)    Whh  = (const float*)d_in[i];
        else if (s == 4*H_) { if (seen80++ == 0) bih = (const float*)d_in[i]; else bhh = (const float*)d_in[i]; }
        else if (s == H_)   { if (seen20++ == 0) Wa  = (const float*)d_in[i]; else Wb  = (const float*)d_in[i]; }
        else if (s == 1)    { if (seen1++  == 0) ba  = (const float*)d_in[i]; else bb  = (const float*)d_in[i]; }
    }

    float* out = (float*)d_out;
    xg_kernel<<<256, 160>>>(x, lens, Wih, bih, bhh);
    recur_kernel<<<512, 128>>>(lens, Whh);
    head_kernel<<<(T_ * B_) / 256, 256>>>(lens, Wa, ba, Wb, bb, out);
}

// round 9
// speedup vs baseline: 1.5932x; 1.5932x over previous
#include <cuda_runtime.h>
#include <math.h>

#define T_  512
#define B_  2048
#define I_  24
#define H_  20

// Scratch xg[t][b][u] = float4(i,f,g,o). 8 pad timesteps so recur's depth-4
// prefetch (reads up to t ~ mylen+6) stays in-bounds.
__device__ float4 g_xg[(size_t)(T_ + 8) * B_ * H_];
// h[t][b][u] for the head pass.
__device__ float  g_h[(size_t)T_ * B_ * H_];

__device__ __forceinline__ float tanhx(float x) {
    float r; asm("tanh.approx.f32 %0,%1;" : "=f"(r) : "f"(x)); return r;
}
__device__ __forceinline__ float sigx(float x) {   // sigmoid via HW tanh
    return fmaf(0.5f, tanhx(0.5f * x), 0.5f);
}

// ---------------------------------------------------------------------------
// Kernel 1: xg = x @ W_ih^T + (b_ih+b_hh) for t < len[b].
// Block = 8 CONSECUTIVE b-columns x 20 units (160 thr) over a 64-step
// t-chunk. Consecutive b => near-equal lengths (sorted) => ~full lane
// utilization. Weights in registers (96 floats, amortized over the chunk).
// Store: thread (j,u) writes float4 (i,f,g,o) at (t, b0+j, u); address =
// block_base + tid -> one contiguous 2560B span per t, fully coalesced,
// directly in recur's layout. x rows: 20 threads share addrs -> L1 bcast.
// ---------------------------------------------------------------------------
#define XG_CHUNK 64
__global__ __launch_bounds__(160, 3)
void xg_kernel(const float* __restrict__ x,
               const int*   __restrict__ lens,
               const float* __restrict__ Wih,
               const float* __restrict__ bih,
               const float* __restrict__ bhh)
{
    const int slab = blockIdx.x >> 3;         // 0..255
    const int chn  = blockIdx.x & 7;          // 0..7
    const int t0   = chn * XG_CHUNK;
    const int b0   = slab * 8;

    const int lmax = lens[b0];                // max length in slab (sorted)
    if (t0 >= lmax) return;                   // whole chunk masked
    const int tend = min(t0 + XG_CHUNK, lmax);

    const int tid = threadIdx.x;
    const int j   = tid / H_;                 // column 0..7
    const int u   = tid % H_;                 // unit 0..19
    const int b   = b0 + j;
    const int mylen = lens[b];

    float w0[I_], w1[I_], w2[I_], w3[I_];
    #pragma unroll
    for (int k = 0; k < I_; k++) {
        w0[k] = Wih[(0*H_ + u) * I_ + k];
        w1[k] = Wih[(1*H_ + u) * I_ + k];
        w2[k] = Wih[(2*H_ + u) * I_ + k];
        w3[k] = Wih[(3*H_ + u) * I_ + k];
    }
    float4 bias;
    bias.x = bih[0*H_ + u] + bhh[0*H_ + u];
    bias.y = bih[1*H_ + u] + bhh[1*H_ + u];
    bias.z = bih[2*H_ + u] + bhh[2*H_ + u];
    bias.w = bih[3*H_ + u] + bhh[3*H_ + u];

    const float4* xp  = (const float4*)(x + ((size_t)t0 * B_ + b) * I_);
    const size_t  xstr = (size_t)B_ * I_ / 4;             // per-t, in float4s
    float4*       op  = &g_xg[((size_t)t0 * B_ + b) * H_ + u];
    const size_t  ostr = (size_t)B_ * H_;

    for (int t = t0; t < tend; t++) {
        float4 a = bias;
        #pragma unroll
        for (int q = 0; q < 6; q++) {
            float4 v = xp[q];                 // L1-broadcast across the column
            a.x = fmaf(w0[4*q+0], v.x, a.x); a.x = fmaf(w0[4*q+1], v.y, a.x);
            a.x = fmaf(w0[4*q+2], v.z, a.x); a.x = fmaf(w0[4*q+3], v.w, a.x);
            a.y = fmaf(w1[4*q+0], v.x, a.y); a.y = fmaf(w1[4*q+1], v.y, a.y);
            a.y = fmaf(w1[4*q+2], v.z, a.y); a.y = fmaf(w1[4*q+3], v.w, a.y);
            a.z = fmaf(w2[4*q+0], v.x, a.z); a.z = fmaf(w2[4*q+1], v.y, a.z);
            a.z = fmaf(w2[4*q+2], v.z, a.z); a.z = fmaf(w2[4*q+3], v.w, a.z);
            a.w = fmaf(w3[4*q+0], v.x, a.w); a.w = fmaf(w3[4*q+1], v.y, a.w);
            a.w = fmaf(w3[4*q+2], v.z, a.w); a.w = fmaf(w3[4*q+3], v.w, a.w);
        }
        if (t < mylen) *op = a;               // coalesced block-wide store
        xp += xstr;
        op += ostr;
    }
}

// ---------------------------------------------------------------------------
// Kernel 2: recurrence, one warp per batch element, t < len[b] only.
// Gate loads coalesced (320B/warp-step), prefetched FOUR steps ahead via a
// rotated register buffer. Steps past mylen compute on in-bounds pad garbage
// but never store.
// ---------------------------------------------------------------------------
__global__ __launch_bounds__(128, 4)
void recur_kernel(const int*   __restrict__ lens,
                  const float* __restrict__ Whh)
{
    const int lane = threadIdx.x & 31;
    const int wid  = threadIdx.x >> 5;
    const int j    = blockIdx.x;
    const int b    = (wid < 2) ? (2*j + wid) : (2047 - 2*j - (wid - 2));
    const int uu   = (lane < H_) ? lane : 0;      // lanes 20..31 mirror u=0

    float wi[H_], wf[H_], wg[H_], wo[H_];
    #pragma unroll
    for (int k = 0; k < H_; k++) {
        wi[k] = Whh[(0*H_ + uu) * H_ + k];
        wf[k] = Whh[(1*H_ + uu) * H_ + k];
        wg[k] = Whh[(2*H_ + uu) * H_ + k];
        wo[k] = Whh[(3*H_ + uu) * H_ + k];
    }
    const int mylen = lens[b];                    // >= 1

    float h = 0.0f, c = 0.0f;

    const float4* xp = &g_xg[(size_t)b * H_ + uu];
    const size_t  xstride = (size_t)B_ * H_;
    float4 q0 = xp[0];
    float4 q1 = xp[xstride];
    float4 q2 = xp[2*xstride];
    float4 q3 = xp[3*xstride];
    xp += 4 * xstride;                            // next refill row

    float* hp = &g_h[(size_t)b * H_ + lane];

    #define RSTEP(QBUF, TOFF)                                            \
    {                                                                    \
        float ai = QBUF.x, af = QBUF.y, ag = QBUF.z, ao = QBUF.w;        \
        _Pragma("unroll")                                                \
        for (int k = 0; k < H_; k++) {                                   \
            float hk = __shfl_sync(0xffffffffu, h, k);                   \
            ai = fmaf(wi[k], hk, ai);                                    \
            af = fmaf(wf[k], hk, af);                                    \
            ag = fmaf(wg[k], hk, ag);                                    \
            ao = fmaf(wo[k], hk, ao);                                    \
        }                                                                \
        c = fmaf(sigx(af), c, sigx(ai) * tanhx(ag));                     \
        h = sigx(ao) * tanhx(c);                                         \
        if (lane < H_ && (t + TOFF) < mylen)                             \
            hp[(size_t)(t + TOFF) * (B_ * H_)] = h;                      \
        QBUF = *xp;                               /* refill t+TOFF+4 */  \
        xp += xstride;                                                   \
    }

    for (int t = 0; t < mylen; t += 4) {
        RSTEP(q0, 0)
        RSTEP(q1, 1)
        RSTEP(q2, 2)
        RSTEP(q3, 3)
    }
    #undef RSTEP
}

// ---------------------------------------------------------------------------
// Kernel 3: heads + padding over the full [T, B] grid.
// ---------------------------------------------------------------------------
__global__ __launch_bounds__(256)
void head_kernel(const int*   __restrict__ lens,
                 const float* __restrict__ Wa,
                 const float* __restrict__ ba,
                 const float* __restrict__ Wb,
                 const float* __restrict__ bb,
                 float* __restrict__ out)
{
    const int idx = blockIdx.x * 256 + threadIdx.x;   // t*B + b
    const int b   = idx & (B_ - 1);
    const int t   = idx >> 11;

    float za = ba[0], zb = bb[0];
    if (t < lens[b]) {
        float4 hq[5];
        const float4* hp = (const float4*)&g_h[(size_t)idx * H_];
        #pragma unroll
        for (int q = 0; q < 5; q++) hq[q] = hp[q];
        const float* hv = (const float*)hq;
        #pragma unroll
        for (int k = 0; k < H_; k++) {
            za = fmaf(hv[k], Wa[k], za);
            zb = fmaf(hv[k], Wb[k], zb);
        }
    }
    out[idx] = __expf(za);
    out[(size_t)T_ * B_ + idx] =
        fmaxf(zb, 0.0f) + __logf(1.0f + __expf(-fabsf(zb)));
}

extern "C" void kernel_launch(void* const* d_in, const int* in_sizes, int n_in,
                              void* d_out, int out_size)
{
    const float *x = 0, *Wih = 0, *Whh = 0, *bih = 0, *bhh = 0;
    const float *Wa = 0, *ba = 0, *Wb = 0, *bb = 0;
    const int *lens = 0;
    int seen80 = 0, seen20 = 0, seen1 = 0;
    for (int i = 0; i < n_in; i++) {
        int s = in_sizes[i];
        if      (s == T_ * B_ * I_) x    = (const float*)d_in[i];
        else if (s == B_)           lens = (const int*)d_in[i];
        else if (s == 4*H_ * I_)    Wih  = (const float*)d_in[i];
        else if (s == 4*H_ * H_)    Whh  = (const float*)d_in[i];
        else if (s == 4*H_) { if (seen80++ == 0) bih = (const float*)d_in[i]; else bhh = (const float*)d_in[i]; }
        else if (s == H_)   { if (seen20++ == 0) Wa  = (const float*)d_in[i]; else Wb  = (const float*)d_in[i]; }
        else if (s == 1)    { if (seen1++  == 0) ba  = (const float*)d_in[i]; else bb  = (const float*)d_in[i]; }
    }

    float* out = (float*)d_out;
    xg_kernel<<<256 * 8, 160>>>(x, lens, Wih, bih, bhh);
    recur_kernel<<<512, 128>>>(lens, Whh);
    head_kernel<<<(T_ * B_) / 256, 256>>>(lens, Wa, ba, Wb, bb, out);
}

// round 10
// speedup vs baseline: 1.6395x; 1.0291x over previous
#include <cuda_runtime.h>
#include <math.h>

#define T_  512
#define B_  2048
#define I_  24
#define H_  20

// Scratch xg[t][b][u] = float4(i,f,g,o). 8 pad timesteps so recur's depth-4
// prefetch (reads up to t ~ mylen+6) stays in-bounds.
__device__ float4 g_xg[(size_t)(T_ + 8) * B_ * H_];
// h[t][b][u] for the head pass.
__device__ float  g_h[(size_t)T_ * B_ * H_];

__device__ __forceinline__ float tanhx(float x) {
    float r; asm("tanh.approx.f32 %0,%1;" : "=f"(r) : "f"(x)); return r;
}
__device__ __forceinline__ float sigx(float x) {   // sigmoid via HW tanh
    return fmaf(0.5f, tanhx(0.5f * x), 0.5f);
}

// ---------------------------------------------------------------------------
// Kernel 1: xg = x @ W_ih^T + (b_ih+b_hh) for t < len[b].
// Thread = (column j 0..3, unit u, gate-pair p): 48 weight regs (2 gate
// rows), TWO timesteps per iteration (12 LDG up front, 96 FMA, 2 STG.64) so
// DRAM latency is exposed once per two steps. tid = j*40 + u*2 + p makes
// the float2 stores contiguous (coalesced) in recur's [t][b][u] layout.
// x rows: all 40 threads of a column read identical addresses (L1 bcast).
// 4 consecutive b per block -> near-equal lengths (sorted) -> full lanes.
// ---------------------------------------------------------------------------
#define XG_CHUNK 64
__global__ __launch_bounds__(160, 3)
void xg_kernel(const float* __restrict__ x,
               const int*   __restrict__ lens,
               const float* __restrict__ Wih,
               const float* __restrict__ bih,
               const float* __restrict__ bhh)
{
    const int slab = blockIdx.x >> 3;         // 0..511 (4 b each)
    const int chn  = blockIdx.x & 7;          // 0..7
    const int t0   = chn * XG_CHUNK;
    const int b0   = slab * 4;

    const int lmax = lens[b0];                // max length in slab (sorted)
    if (t0 >= lmax) return;                   // whole chunk masked
    const int tend = min(t0 + XG_CHUNK, lmax);

    const int tid = threadIdx.x;
    const int j   = tid / 40;                 // column 0..3
    const int r   = tid % 40;
    const int u   = r >> 1;                   // unit 0..19
    const int p   = r & 1;                    // gate pair: 0=(i,f) 1=(g,o)
    const int b   = b0 + j;
    const int mylen = lens[b];

    const int g0 = 2 * p, g1 = 2 * p + 1;
    float w0[I_], w1[I_];
    #pragma unroll
    for (int k = 0; k < I_; k++) {
        w0[k] = Wih[(g0 * H_ + u) * I_ + k];
        w1[k] = Wih[(g1 * H_ + u) * I_ + k];
    }
    float2 bias;
    bias.x = bih[g0 * H_ + u] + bhh[g0 * H_ + u];
    bias.y = bih[g1 * H_ + u] + bhh[g1 * H_ + u];

    const size_t xstr = (size_t)B_ * I_ / 4;              // per-t, in float4s
    const size_t ostr = (size_t)B_ * H_ * 2;              // per-t, in float2s
    const float4* xbase = (const float4*)(x + (size_t)b * I_);
    float2* op = (float2*)g_xg + ((size_t)t0 * B_ + b) * H_ * 2 + u * 2 + p;

    for (int t = t0; t < tend; t += 2) {
        const int t2 = min(t + 1, T_ - 1);    // clamped (store predicated)
        const float4* pa = xbase + (size_t)t  * xstr;
        const float4* pb = xbase + (size_t)t2 * xstr;

        float4 va0 = pa[0], va1 = pa[1], va2 = pa[2];
        float4 va3 = pa[3], va4 = pa[4], va5 = pa[5];
        float4 vb0 = pb[0], vb1 = pb[1], vb2 = pb[2];
        float4 vb3 = pb[3], vb4 = pb[4], vb5 = pb[5];

        float xa[I_] = { va0.x,va0.y,va0.z,va0.w, va1.x,va1.y,va1.z,va1.w,
                         va2.x,va2.y,va2.z,va2.w, va3.x,va3.y,va3.z,va3.w,
                         va4.x,va4.y,va4.z,va4.w, va5.x,va5.y,va5.z,va5.w };
        float xb[I_] = { vb0.x,vb0.y,vb0.z,vb0.w, vb1.x,vb1.y,vb1.z,vb1.w,
                         vb2.x,vb2.y,vb2.z,vb2.w, vb3.x,vb3.y,vb3.z,vb3.w,
                         vb4.x,vb4.y,vb4.z,vb4.w, vb5.x,vb5.y,vb5.z,vb5.w };

        float2 aa = bias, ab = bias;
        #pragma unroll
        for (int k = 0; k < I_; k++) {
            aa.x = fmaf(w0[k], xa[k], aa.x);
            aa.y = fmaf(w1[k], xa[k], aa.y);
            ab.x = fmaf(w0[k], xb[k], ab.x);
            ab.y = fmaf(w1[k], xb[k], ab.y);
        }

        if (t < mylen)     op[0]    = aa;     // coalesced float2 stores
        if (t + 1 < mylen) op[ostr] = ab;
        op += 2 * ostr;
    }
}

// ---------------------------------------------------------------------------
// Kernel 2: recurrence, one warp per batch element, t < len[b] only.
// Gate loads coalesced (320B/warp-step), prefetched FOUR steps ahead via a
// rotated register buffer. Steps past mylen compute on in-bounds pad garbage
// but never store.
// ---------------------------------------------------------------------------
__global__ __launch_bounds__(128, 4)
void recur_kernel(const int*   __restrict__ lens,
                  const float* __restrict__ Whh)
{
    const int lane = threadIdx.x & 31;
    const int wid  = threadIdx.x >> 5;
    const int j    = blockIdx.x;
    const int b    = (wid < 2) ? (2*j + wid) : (2047 - 2*j - (wid - 2));
    const int uu   = (lane < H_) ? lane : 0;      // lanes 20..31 mirror u=0

    float wi[H_], wf[H_], wg[H_], wo[H_];
    #pragma unroll
    for (int k = 0; k < H_; k++) {
        wi[k] = Whh[(0*H_ + uu) * H_ + k];
        wf[k] = Whh[(1*H_ + uu) * H_ + k];
        wg[k] = Whh[(2*H_ + uu) * H_ + k];
        wo[k] = Whh[(3*H_ + uu) * H_ + k];
    }
    const int mylen = lens[b];                    // >= 1

    float h = 0.0f, c = 0.0f;

    const float4* xp = &g_xg[(size_t)b * H_ + uu];
    const size_t  xstride = (size_t)B_ * H_;
    float4 q0 = xp[0];
    float4 q1 = xp[xstride];
    float4 q2 = xp[2*xstride];
    float4 q3 = xp[3*xstride];
    xp += 4 * xstride;                            // next refill row

    float* hp = &g_h[(size_t)b * H_ + lane];

    #define RSTEP(QBUF, TOFF)                                            \
    {                                                                    \
        float ai = QBUF.x, af = QBUF.y, ag = QBUF.z, ao = QBUF.w;        \
        _Pragma("unroll")                                                \
        for (int k = 0; k < H_; k++) {                                   \
            float hk = __shfl_sync(0xffffffffu, h, k);                   \
            ai = fmaf(wi[k], hk, ai);                                    \
            af = fmaf(wf[k], hk, af);                                    \
            ag = fmaf(wg[k], hk, ag);                                    \
            ao = fmaf(wo[k], hk, ao);                                    \
        }                                                                \
        c = fmaf(sigx(af), c, sigx(ai) * tanhx(ag));                     \
        h = sigx(ao) * tanhx(c);                                         \
        if (lane < H_ && (t + TOFF) < mylen)                             \
            hp[(size_t)(t + TOFF) * (B_ * H_)] = h;                      \
        QBUF = *xp;                               /* refill t+TOFF+4 */  \
        xp += xstride;                                                   \
    }

    for (int t = 0; t < mylen; t += 4) {
        RSTEP(q0, 0)
        RSTEP(q1, 1)
        RSTEP(q2, 2)
        RSTEP(q3, 3)
    }
    #undef RSTEP
}

// ---------------------------------------------------------------------------
// Kernel 3: heads + padding over the full [T, B] grid.
// ---------------------------------------------------------------------------
__global__ __launch_bounds__(256)
void head_kernel(const int*   __restrict__ lens,
                 const float* __restrict__ Wa,
                 const float* __restrict__ ba,
                 const float* __restrict__ Wb,
                 const float* __restrict__ bb,
                 float* __restrict__ out)
{
    const int idx = blockIdx.x * 256 + threadIdx.x;   // t*B + b
    const int b   = idx & (B_ - 1);
    const int t   = idx >> 11;

    float za = ba[0], zb = bb[0];
    if (t < lens[b]) {
        float4 hq[5];
        const float4* hp = (const float4*)&g_h[(size_t)idx * H_];
        #pragma unroll
        for (int q = 0; q < 5; q++) hq[q] = hp[q];
        const float* hv = (const float*)hq;
        #pragma unroll
        for (int k = 0; k < H_; k++) {
            za = fmaf(hv[k], Wa[k], za);
            zb = fmaf(hv[k], Wb[k], zb);
        }
    }
    out[idx] = __expf(za);
    out[(size_t)T_ * B_ + idx] =
        fmaxf(zb, 0.0f) + __logf(1.0f + __expf(-fabsf(zb)));
}

extern "C" void kernel_launch(void* const* d_in, const int* in_sizes, int n_in,
                              void* d_out, int out_size)
{
    const float *x = 0, *Wih = 0, *Whh = 0, *bih = 0, *bhh = 0;
    const float *Wa = 0, *ba = 0, *Wb = 0, *bb = 0;
    const int *lens = 0;
    int seen80 = 0, seen20 = 0, seen1 = 0;
    for (int i = 0; i < n_in; i++) {
        int s = in_sizes[i];
        if      (s == T_ * B_ * I_) x    = (const float*)d_in[i];
        else if (s == B_)           lens = (const int*)d_in[i];
        else if (s == 4*H_ * I_)    Wih  = (const float*)d_in[i];
        else if (s == 4*H_ * H_)    Whh  = (const float*)d_in[i];
        else if (s == 4*H_) { if (seen80++ == 0) bih = (const float*)d_in[i]; else bhh = (const float*)d_in[i]; }
        else if (s == H_)   { if (seen20++ == 0) Wa  = (const float*)d_in[i]; else Wb  = (const float*)d_in[i]; }
        else if (s == 1)    { if (seen1++  == 0) ba  = (const float*)d_in[i]; else bb  = (const float*)d_in[i]; }
    }

    float* out = (float*)d_out;
    xg_kernel<<<512 * 8, 160>>>(x, lens, Wih, bih, bhh);
    recur_kernel<<<512, 128>>>(lens, Whh);
    head_kernel<<<(T_ * B_) / 256, 256>>>(lens, Wa, ba, Wb, bb, out);
}